// round 14
// baseline (speedup 1.0000x reference)
#include <cuda_runtime.h>
#include <math_constants.h>

// Roi_61564061221098 round 14: NHWC merged row-sweep.
// R12 block layout (roi x ph-half; 8 warps = 4 ch-slices x 2 pw-groups) but
// each warp sweeps h ONCE over its half, and per row makes one merged
// 4-wide-batched pass over its contiguous column range, accumulating into 4
// pw-bin accs via warp-uniform predicates. Adjacent-ph 1-row overlap is
// carried in registers. Every position is loaded once -> ~34% less L2 traffic
// than R12 at the same MLP.

#define NC    512
#define NC4   (NC / 4)
#define FH    50
#define FW    68
#define NPOS  (FH * FW)          // 3400
#define PP    7
#define SCALE 0.0625f
#define NEG_INF (-CUDART_INF_F)
#define SSTR  517                // sbin row stride (coprime with 32 banks)
#define NB0   28                 // bins in half 0 (ph 0..3)
#define NB1   21                 // bins in half 1 (ph 4..6)
#define SMEMB (NB0 * SSTR * 4)   // 57,904 B

__device__ float4 g_nhwc4[4 * NPOS * NC4 + 4 * 32];   // +pad: unguarded overreads
// per-roi record: [0]=image n, [3..9] = hs | he<<8 | ws<<16 | we<<24 (absolute)
__device__ __align__(16) int g_rec[4096 * 16];

__global__ void transpose_kernel(const float* __restrict__ x)
{
    __shared__ float tile[32][33];
    const int n  = blockIdx.z;
    const int c0 = blockIdx.y * 32;
    const int p0 = blockIdx.x * 32;
    const int tx = threadIdx.x, ty = threadIdx.y;    // block (32, 8)
    float* __restrict__ dst = (float*)g_nhwc4;

#pragma unroll
    for (int dy = 0; dy < 32; dy += 8) {
        const int c = c0 + ty + dy;
        const int p = p0 + tx;
        tile[ty + dy][tx] = (p < NPOS) ? x[(n * NC + c) * NPOS + p] : 0.0f;
    }
    __syncthreads();
#pragma unroll
    for (int dy = 0; dy < 32; dy += 8) {
        const int p = p0 + ty + dy;
        if (p < NPOS) dst[((size_t)n * NPOS + p) * NC + c0 + tx] = tile[tx][ty + dy];
    }
}

__global__ void roi_prep(const float* __restrict__ rois,
                         const int*   __restrict__ ridx, int R)
{
    int r = blockIdx.x * blockDim.x + threadIdx.x;
    if (r >= R) return;

    const float y1 = rois[r * 4 + 0];
    const float x1 = rois[r * 4 + 1];
    const float y2 = rois[r * 4 + 2];
    const float x2 = rois[r * 4 + 3];
    const float rb0 = rintf(__fmul_rn(x1, SCALE));
    const float rb1 = rintf(__fmul_rn(y1, SCALE));
    const float rb2 = rintf(__fmul_rn(x2, SCALE));
    const float rb3 = rintf(__fmul_rn(y2, SCALE));
    const float roiw = fmaxf(__fadd_rn(__fsub_rn(rb2, rb0), 1.0f), 1.0f);
    const float roih = fmaxf(__fadd_rn(__fsub_rn(rb3, rb1), 1.0f), 1.0f);
    const float R7 = (float)(1.0 / 7.0);          // XLA: x/7 -> x * fl(1/7)
    const float bw = __fmul_rn(roiw, R7);
    const float bh = __fmul_rn(roih, R7);

    int* rec = g_rec + r * 16;
    rec[0] = ridx[r];
#pragma unroll
    for (int p = 0; p < PP; p++) {
        const float fp  = (float)p;
        const float fp1 = (float)(p + 1);
        int hs = (int)fminf(fmaxf(__fadd_rn(floorf(__fmul_rn(fp,  bh)), rb1), 0.0f), (float)FH);
        int he = (int)fminf(fmaxf(__fadd_rn(ceilf (__fmul_rn(fp1, bh)), rb1), 0.0f), (float)FH);
        int ws = (int)fminf(fmaxf(__fadd_rn(floorf(__fmul_rn(fp,  bw)), rb0), 0.0f), (float)FW);
        int we = (int)fminf(fmaxf(__fadd_rn(ceilf (__fmul_rn(fp1, bw)), rb0), 0.0f), (float)FW);
        rec[3 + p] = hs | (he << 8) | (ws << 16) | (we << 24);
    }
}

__device__ __forceinline__ void fmax4(float4& a, const float4 b)
{
    a.x = fmaxf(a.x, b.x); a.y = fmaxf(a.y, b.y);
    a.z = fmaxf(a.z, b.z); a.w = fmaxf(a.w, b.w);
}

template <int HALF>
__global__ __launch_bounds__(256, 3)
void roi_pool(float* __restrict__ out, int R)
{
    extern __shared__ float sbin[];                 // [nb][SSTR]

    const int r    = blockIdx.x;
    const int tid  = threadIdx.x;
    const int warp = tid >> 5;
    const int lane = tid & 31;
    const int chid = warp & 3;          // 128-channel slice
    const int pwg  = warp >> 2;         // 0: pw 0-3, 1: pw 4-6

    int v = 0;
    if (lane < 16) v = g_rec[r * 16 + lane];
    const int n = __shfl_sync(0xffffffffu, v, 0);

    const float4* __restrict__ base =
        g_nhwc4 + (size_t)n * NPOS * NC4 + chid * 32 + lane;

    const int npw = pwg ? 3 : 4;
    const int pw0 = pwg * 4;
    int wsA[4], weA[4];
#pragma unroll
    for (int i = 0; i < 4; i++) {
        if (i < npw) {
            const int qk = __shfl_sync(0xffffffffu, v, 3 + pw0 + i);
            wsA[i] = (qk >> 16) & 0xff;
            weA[i] = (qk >> 24) & 0xff;
        } else { wsA[i] = 0; weA[i] = 0; }           // empty: predicates false
    }
    const int wlo   = wsA[0];
    const int whi   = weA[npw - 1];
    const int ncols = whi - wlo;

    constexpr int phN = HALF ? 3 : 4;
    constexpr int ph0 = HALF ? 4 : 0;

    const float4 NI4 = make_float4(NEG_INF, NEG_INF, NEG_INF, NEG_INF);
    float4 racc[4] = {NI4, NI4, NI4, NI4};   // last processed row, per pw bin
    int prevh1 = -1000;

#pragma unroll
    for (int phi = 0; phi < phN; phi++) {
        const int pk = __shfl_sync(0xffffffffu, v, 3 + ph0 + phi);
        const int h0 = pk & 0xff;
        const int h1 = (pk >> 8) & 0xff;
        const bool hnon = h0 < h1;
        const bool seed = hnon && (h0 == prevh1 - 1);   // boundary row carried
        const int  hb   = seed ? h0 + 1 : h0;

        float4 cur[4];
#pragma unroll
        for (int i = 0; i < 4; i++) cur[i] = seed ? racc[i] : NI4;

        for (int h = hb; h < h1; h++) {
#pragma unroll
            for (int i = 0; i < 4; i++) racc[i] = NI4;
            const float4* pr = base + (h * FW + wlo) * NC4;
            for (int wb = 0; wb < ncols; wb += 4) {
                // 4 independent loads issued before any FMAX (MLP 4)
                const float4 v0 = pr[0];
                const float4 v1 = pr[NC4];
                const float4 v2 = pr[2 * NC4];
                const float4 v3 = pr[3 * NC4];
                const int wc = wlo + wb;
#pragma unroll
                for (int i = 0; i < 4; i++) {        // warp-uniform predicates
                    if (wc     >= wsA[i] && wc     < weA[i]) fmax4(racc[i], v0);
                    if (wc + 1 >= wsA[i] && wc + 1 < weA[i]) fmax4(racc[i], v1);
                    if (wc + 2 >= wsA[i] && wc + 2 < weA[i]) fmax4(racc[i], v2);
                    if (wc + 3 >= wsA[i] && wc + 3 < weA[i]) fmax4(racc[i], v3);
                }
                pr += 4 * NC4;
            }
#pragma unroll
            for (int i = 0; i < 4; i++) fmax4(cur[i], racc[i]);
        }
        // racc now holds the last row read (or, for a seed-only bin, the
        // previous carried row — which IS this bin's row). Valid next-carry.
        if (hnon) prevh1 = h1;

        // store (empty bin / all -inf -> 0.0 per reference isfinite rule)
#pragma unroll
        for (int i = 0; i < 4; i++) {
            if (i >= npw) break;
            const int b = phi * PP + pw0 + i;
            float* s = sbin + b * SSTR + chid * 128 + lane * 4;
            s[0] = (cur[i].x == NEG_INF) ? 0.0f : cur[i].x;
            s[1] = (cur[i].y == NEG_INF) ? 0.0f : cur[i].y;
            s[2] = (cur[i].z == NEG_INF) ? 0.0f : cur[i].z;
            s[3] = (cur[i].w == NEG_INF) ? 0.0f : cur[i].w;
        }
    }
    __syncthreads();

    // flush: out[r][ch][HALF ? 28+b : b]
    constexpr int NB = HALF ? NB1 : NB0;
    const size_t ob = (size_t)r * (NC * 49) + (HALF ? NB0 : 0);
    for (int i = tid; i < NB * NC; i += 256) {
        const int ch = i / NB;
        const int b  = i - ch * NB;
        out[ob + ch * 49 + b] = sbin[b * SSTR + ch];
    }
}

extern "C" void kernel_launch(void* const* d_in, const int* in_sizes, int n_in,
                              void* d_out, int out_size)
{
    const float* x    = (const float*)d_in[0];
    const float* rois = (const float*)d_in[1];
    const int*   ridx = (const int*)d_in[2];
    float*       out  = (float*)d_out;
    const int R = in_sizes[2];

    cudaFuncSetAttribute(roi_pool<0>, cudaFuncAttributeMaxDynamicSharedMemorySize, SMEMB);
    cudaFuncSetAttribute(roi_pool<1>, cudaFuncAttributeMaxDynamicSharedMemorySize, SMEMB);

    dim3 tgrid((NPOS + 31) / 32, NC / 32, 4);
    transpose_kernel<<<tgrid, dim3(32, 8)>>>(x);
    roi_prep<<<(R + 255) / 256, 256>>>(rois, ridx, R);
    roi_pool<0><<<R, 256, SMEMB>>>(out, R);
    roi_pool<1><<<R, 256, SMEMB>>>(out, R);
}

// round 15
// speedup vs baseline: 1.1193x; 1.1193x over previous
#include <cuda_runtime.h>
#include <math_constants.h>

// Roi_61564061221098 round 15: NHWC + carry-chained overlap dedupe.
// R12 block layout (block = roi x ph-half; 8 warps = 4 ch-slices x 2 pw-groups,
// 58KB sbin, 3 blocks/SM). Per ph, rows are swept once; per row each warp's
// 4 pw bins are processed left->right with batched float4 loads. Dedupe:
//  - column: bin i's last-column value (loaded anyway) is carried as bin
//    i+1's overlap column -> one FMAX, no re-load.
//  - row: the last row's full-bin row max seeds the next ph (overlap <= 1
//    row), so reads start at h0+1.
// All carries re-use identical values -> bit-exact (max is order-independent).

#define NC    512
#define NC4   (NC / 4)
#define FH    50
#define FW    68
#define NPOS  (FH * FW)          // 3400
#define PP    7
#define SCALE 0.0625f
#define NEG_INF (-CUDART_INF_F)
#define SSTR  517                // sbin row stride (coprime with 32 banks)
#define NB0   28                 // bins in half 0 (ph 0..3)
#define NB1   21                 // bins in half 1 (ph 4..6)
#define SMEMB (NB0 * SSTR * 4)   // 57,904 B

__device__ float4 g_nhwc4[4 * NPOS * NC4 + 32];
// per-roi record: [0]=image n, [3..9] = hs | he<<8 | ws<<16 | we<<24 (absolute)
__device__ __align__(16) int g_rec[4096 * 16];

__global__ void transpose_kernel(const float* __restrict__ x)
{
    __shared__ float tile[32][33];
    const int n  = blockIdx.z;
    const int c0 = blockIdx.y * 32;
    const int p0 = blockIdx.x * 32;
    const int tx = threadIdx.x, ty = threadIdx.y;    // block (32, 8)
    float* __restrict__ dst = (float*)g_nhwc4;

#pragma unroll
    for (int dy = 0; dy < 32; dy += 8) {
        const int c = c0 + ty + dy;
        const int p = p0 + tx;
        tile[ty + dy][tx] = (p < NPOS) ? x[(n * NC + c) * NPOS + p] : 0.0f;
    }
    __syncthreads();
#pragma unroll
    for (int dy = 0; dy < 32; dy += 8) {
        const int p = p0 + ty + dy;
        if (p < NPOS) dst[((size_t)n * NPOS + p) * NC + c0 + tx] = tile[tx][ty + dy];
    }
}

__global__ void roi_prep(const float* __restrict__ rois,
                         const int*   __restrict__ ridx, int R)
{
    int r = blockIdx.x * blockDim.x + threadIdx.x;
    if (r >= R) return;

    const float y1 = rois[r * 4 + 0];
    const float x1 = rois[r * 4 + 1];
    const float y2 = rois[r * 4 + 2];
    const float x2 = rois[r * 4 + 3];
    const float rb0 = rintf(__fmul_rn(x1, SCALE));
    const float rb1 = rintf(__fmul_rn(y1, SCALE));
    const float rb2 = rintf(__fmul_rn(x2, SCALE));
    const float rb3 = rintf(__fmul_rn(y2, SCALE));
    const float roiw = fmaxf(__fadd_rn(__fsub_rn(rb2, rb0), 1.0f), 1.0f);
    const float roih = fmaxf(__fadd_rn(__fsub_rn(rb3, rb1), 1.0f), 1.0f);
    const float R7 = (float)(1.0 / 7.0);          // XLA: x/7 -> x * fl(1/7)
    const float bw = __fmul_rn(roiw, R7);
    const float bh = __fmul_rn(roih, R7);

    int* rec = g_rec + r * 16;
    rec[0] = ridx[r];
#pragma unroll
    for (int p = 0; p < PP; p++) {
        const float fp  = (float)p;
        const float fp1 = (float)(p + 1);
        int hs = (int)fminf(fmaxf(__fadd_rn(floorf(__fmul_rn(fp,  bh)), rb1), 0.0f), (float)FH);
        int he = (int)fminf(fmaxf(__fadd_rn(ceilf (__fmul_rn(fp1, bh)), rb1), 0.0f), (float)FH);
        int ws = (int)fminf(fmaxf(__fadd_rn(floorf(__fmul_rn(fp,  bw)), rb0), 0.0f), (float)FW);
        int we = (int)fminf(fmaxf(__fadd_rn(ceilf (__fmul_rn(fp1, bw)), rb0), 0.0f), (float)FW);
        rec[3 + p] = hs | (he << 8) | (ws << 16) | (we << 24);
    }
}

__device__ __forceinline__ void fmax4(float4& a, const float4 b)
{
    a.x = fmaxf(a.x, b.x); a.y = fmaxf(a.y, b.y);
    a.z = fmaxf(a.z, b.z); a.w = fmaxf(a.w, b.w);
}

__global__ __launch_bounds__(256, 3)
void roi_pool(float* __restrict__ out, int R)
{
    extern __shared__ float sbin[];                 // [nb][SSTR]

    const int bid  = blockIdx.x;
    const int r    = bid >> 1;
    const int half = bid & 1;
    const int tid  = threadIdx.x;
    const int warp = tid >> 5;
    const int lane = tid & 31;
    const int chid = warp & 3;          // 128-channel slice
    const int pwg  = warp >> 2;         // 0: pw 0-3, 1: pw 4-6

    int v = 0;
    if (lane < 16) v = g_rec[r * 16 + lane];
    const int n = __shfl_sync(0xffffffffu, v, 0);

    const float4* __restrict__ base =
        g_nhwc4 + (size_t)n * NPOS * NC4 + chid * 32 + lane;

    const int npw = pwg ? 3 : 4;
    const int pw0 = pwg * 4;
    int wsA[4], weA[4], wsE[4];
    bool skipc[4];
#pragma unroll
    for (int i = 0; i < 4; i++) {
        const int qk = __shfl_sync(0xffffffffu, v, 3 + pw0 + (i < npw ? i : 0));
        wsA[i] = (qk >> 16) & 0xff;
        weA[i] = (qk >> 24) & 0xff;
        if (i >= npw) { wsA[i] = 0; weA[i] = 0; }
    }
    skipc[0] = false;
    wsE[0]   = wsA[0];
#pragma unroll
    for (int i = 1; i < 4; i++) {
        // overlap col (<=1) with PREVIOUS bin, and previous bin nonempty
        skipc[i] = (wsA[i] == weA[i - 1] - 1) && (weA[i - 1] > wsA[i - 1]);
        wsE[i]   = wsA[i] + (skipc[i] ? 1 : 0);
    }

    const int phN = half ? 3 : 4;
    const int ph0 = half ? 4 : 0;

    const float4 NI4 = make_float4(NEG_INF, NEG_INF, NEG_INF, NEG_INF);
    float4 rowc[4] = {NI4, NI4, NI4, NI4};   // full-bin max over row (prevh1-1)
    int prevh1 = -1000;

    for (int phi = 0; phi < phN; phi++) {
        const int pk = __shfl_sync(0xffffffffu, v, 3 + ph0 + phi);
        const int h0 = pk & 0xff;
        const int h1 = (pk >> 8) & 0xff;
        const bool hnon = h0 < h1;
        const bool seed = hnon && (h0 == prevh1 - 1);
        const int  hb   = seed ? h0 + 1 : h0;

        float4 acc[4];
#pragma unroll
        for (int i = 0; i < 4; i++) acc[i] = (seed && hnon) ? rowc[i] : NI4;

        for (int h = hb; h < h1; h++) {
            const float4* rowbase = base + (size_t)h * FW * NC4;
            const bool lastrow = (h == h1 - 1);
            float4 prevlast = NI4;           // lv of bin i-1, THIS row
#pragma unroll
            for (int i = 0; i < 4; i++) {
                if (i >= npw) break;
                const float4 carry = prevlast;
                const int a = wsE[i], b = weA[i];
                float4 rm = NI4;
                float4 lv = carry;           // effective-empty bin: shared col
                if (a < b) {
                    const float4* p = rowbase + a * NC4;
                    const int nn = b - 1 - a;        // cols before the last
                    int w = 0;
                    for (; w + 4 <= nn; w += 4) {    // 4 loads in flight
                        const float4 v0 = p[0];
                        const float4 v1 = p[NC4];
                        const float4 v2 = p[2 * NC4];
                        const float4 v3 = p[3 * NC4];
                        fmax4(rm, v0); fmax4(rm, v1);
                        fmax4(rm, v2); fmax4(rm, v3);
                        p += 4 * NC4;
                    }
                    if (w < nn) {                    // remainder 1-3, batched
                        const float4 v0 = p[0];
                        float4 v1, v2;
                        if (w + 1 < nn) v1 = p[NC4];
                        if (w + 2 < nn) v2 = p[2 * NC4];
                        fmax4(rm, v0);
                        if (w + 1 < nn) fmax4(rm, v1);
                        if (w + 2 < nn) fmax4(rm, v2);
                    }
                    lv = rowbase[(b - 1) * NC4];     // bin's last column
                    fmax4(rm, lv);
                }
                if (skipc[i]) fmax4(rm, carry);      // overlap col, no re-load
                fmax4(acc[i], rm);
                if (lastrow) rowc[i] = rm;           // full-bin boundary-row max
                prevlast = lv;
            }
        }
        if (hnon) prevh1 = h1;

        // store (empty bin / all -inf -> 0.0 per reference isfinite rule)
#pragma unroll
        for (int i = 0; i < 4; i++) {
            if (i >= npw) break;
            const int b = phi * PP + pw0 + i;
            float* s = sbin + b * SSTR + chid * 128 + lane * 4;
            s[0] = (acc[i].x == NEG_INF) ? 0.0f : acc[i].x;
            s[1] = (acc[i].y == NEG_INF) ? 0.0f : acc[i].y;
            s[2] = (acc[i].z == NEG_INF) ? 0.0f : acc[i].z;
            s[3] = (acc[i].w == NEG_INF) ? 0.0f : acc[i].w;
        }
    }
    __syncthreads();

    // flush: out[r][ch][half ? 28+b : b]
    const size_t ob = (size_t)r * (NC * 49) + (half ? NB0 : 0);
    if (half == 0) {
        for (int i = tid; i < NB0 * NC; i += 256) {
            const int ch = i / NB0;
            const int b  = i - ch * NB0;
            out[ob + ch * 49 + b] = sbin[b * SSTR + ch];
        }
    } else {
        for (int i = tid; i < NB1 * NC; i += 256) {
            const int ch = i / NB1;
            const int b  = i - ch * NB1;
            out[ob + ch * 49 + b] = sbin[b * SSTR + ch];
        }
    }
}

extern "C" void kernel_launch(void* const* d_in, const int* in_sizes, int n_in,
                              void* d_out, int out_size)
{
    const float* x    = (const float*)d_in[0];
    const float* rois = (const float*)d_in[1];
    const int*   ridx = (const int*)d_in[2];
    float*       out  = (float*)d_out;
    const int R = in_sizes[2];

    cudaFuncSetAttribute(roi_pool, cudaFuncAttributeMaxDynamicSharedMemorySize,
                         SMEMB);

    dim3 tgrid((NPOS + 31) / 32, NC / 32, 4);
    transpose_kernel<<<tgrid, dim3(32, 8)>>>(x);
    roi_prep<<<(R + 255) / 256, 256>>>(rois, ridx, R);
    roi_pool<<<R * 2, 256, SMEMB>>>(out, R);
}

// round 16
// speedup vs baseline: 1.6847x; 1.5052x over previous
#include <cuda_runtime.h>
#include <math_constants.h>

// Roi_61564061221098 round 16: NHWC + h-direction sparse table (range-max).
//  transpose: x -> level-0 NHWC table.
//  build_level k=1..3: T[k][h] = max(T[k-1][h], T[k-1][h+2^(k-1)]).
//  roi_prep:  per ph: k = floor(log2(s-1)) (s<=9 -> k<=3), rows {h0, h1-2^k}.
//             Overlapping lookups are exact (max is idempotent) -> bit-exact.
//  roi_pool:  R12 skeleton (block = roi x ph-half; warps = 4 ch-slices x
//             2 pw-groups; sbin 58KB, 3 blocks/SM) but each bin reads only
//             TWO table rows over its w-range (batched 4 loads in flight).

#define NC    512
#define NC4   (NC / 4)
#define FH    50
#define FW    68
#define NPOS  (FH * FW)          // 3400
#define PP    7
#define SCALE 0.0625f
#define NEG_INF (-CUDART_INF_F)
#define SSTR  517                // sbin row stride (coprime with 32 banks)
#define NB0   28                 // bins in half 0 (ph 0..3)
#define NB1   21                 // bins in half 1 (ph 4..6)
#define SMEMB (NB0 * SSTR * 4)   // 57,904 B
#define LEVS  (4 * NPOS * NC4)   // float4 per level (4 images)

__device__ float4 g_tab[4 * LEVS];   // levels 0..3, 111.4 MB static scratch
// per-roi record: [0]=n, [1..7]=hs|he<<8|h2<<16|k<<24, [8..14]=ws<<16|we<<24
__device__ __align__(16) int g_rec[4096 * 16];

__global__ void transpose_kernel(const float* __restrict__ x)
{
    __shared__ float tile[32][33];
    const int n  = blockIdx.z;
    const int c0 = blockIdx.y * 32;
    const int p0 = blockIdx.x * 32;
    const int tx = threadIdx.x, ty = threadIdx.y;    // block (32, 8)
    float* __restrict__ dst = (float*)g_tab;         // level 0

#pragma unroll
    for (int dy = 0; dy < 32; dy += 8) {
        const int c = c0 + ty + dy;
        const int p = p0 + tx;
        tile[ty + dy][tx] = (p < NPOS) ? x[(n * NC + c) * NPOS + p] : 0.0f;
    }
    __syncthreads();
#pragma unroll
    for (int dy = 0; dy < 32; dy += 8) {
        const int p = p0 + ty + dy;
        if (p < NPOS) dst[((size_t)n * NPOS + p) * NC + c0 + tx] = tile[tx][ty + dy];
    }
}

__device__ __forceinline__ void fmax4(float4& a, const float4 b)
{
    a.x = fmaxf(a.x, b.x); a.y = fmaxf(a.y, b.y);
    a.z = fmaxf(a.z, b.z); a.w = fmaxf(a.w, b.w);
}

__global__ void build_level(int k, int rows)
{
    const int idx = blockIdx.x * 256 + threadIdx.x;
    const int total = 4 * rows * FW * NC4;
    if (idx >= total) return;
    const int c  = idx & (NC4 - 1);
    const int rp = idx >> 7;             // NC4 = 128
    const int w  = rp % FW;
    const int t  = rp / FW;
    const int h  = t % rows;
    const int n  = t / rows;

    const int half = 1 << (k - 1);
    const float4* src = g_tab + (size_t)(k - 1) * LEVS
                        + ((size_t)n * NPOS + h * FW + w) * NC4 + c;
    float4 a = src[0];
    fmax4(a, src[(size_t)half * FW * NC4]);
    g_tab[(size_t)k * LEVS + ((size_t)n * NPOS + h * FW + w) * NC4 + c] = a;
}

__global__ void roi_prep(const float* __restrict__ rois,
                         const int*   __restrict__ ridx, int R)
{
    int r = blockIdx.x * blockDim.x + threadIdx.x;
    if (r >= R) return;

    const float y1 = rois[r * 4 + 0];
    const float x1 = rois[r * 4 + 1];
    const float y2 = rois[r * 4 + 2];
    const float x2 = rois[r * 4 + 3];
    const float rb0 = rintf(__fmul_rn(x1, SCALE));
    const float rb1 = rintf(__fmul_rn(y1, SCALE));
    const float rb2 = rintf(__fmul_rn(x2, SCALE));
    const float rb3 = rintf(__fmul_rn(y2, SCALE));
    const float roiw = fmaxf(__fadd_rn(__fsub_rn(rb2, rb0), 1.0f), 1.0f);
    const float roih = fmaxf(__fadd_rn(__fsub_rn(rb3, rb1), 1.0f), 1.0f);
    const float R7 = (float)(1.0 / 7.0);          // XLA: x/7 -> x * fl(1/7)
    const float bw = __fmul_rn(roiw, R7);
    const float bh = __fmul_rn(roih, R7);

    int* rec = g_rec + r * 16;
    rec[0] = ridx[r];
#pragma unroll
    for (int p = 0; p < PP; p++) {
        const float fp  = (float)p;
        const float fp1 = (float)(p + 1);
        int hs = (int)fminf(fmaxf(__fadd_rn(floorf(__fmul_rn(fp,  bh)), rb1), 0.0f), (float)FH);
        int he = (int)fminf(fmaxf(__fadd_rn(ceilf (__fmul_rn(fp1, bh)), rb1), 0.0f), (float)FH);
        int ws = (int)fminf(fmaxf(__fadd_rn(floorf(__fmul_rn(fp,  bw)), rb0), 0.0f), (float)FW);
        int we = (int)fminf(fmaxf(__fadd_rn(ceilf (__fmul_rn(fp1, bw)), rb0), 0.0f), (float)FW);

        // sparse-table level: k = floor(log2(s-1)) for s>=2 (covers s<=2^k+2^k)
        const int s = he - hs;
        int k = 0, h2 = hs;
        if (s >= 2) {
            k = 31 - __clz(s - 1);
            if (k > 3) k = 3;
            h2 = he - (1 << k);
        }
        rec[1 + p] = hs | (he << 8) | (h2 << 16) | (k << 24);
        rec[8 + p] = (ws << 16) | (we << 24);
    }
}

__global__ __launch_bounds__(256, 3)
void roi_pool(float* __restrict__ out, int R)
{
    extern __shared__ float sbin[];                 // [nb][SSTR]

    const int bid  = blockIdx.x;
    const int r    = bid >> 1;
    const int half = bid & 1;
    const int tid  = threadIdx.x;
    const int warp = tid >> 5;
    const int lane = tid & 31;
    const int chid = warp & 3;          // 128-channel slice
    const int pwg  = warp >> 2;         // 0: pw 0-3, 1: pw 4-6

    int v = 0;
    if (lane < 16) v = g_rec[r * 16 + lane];
    const int n = __shfl_sync(0xffffffffu, v, 0);

    const int npw = pwg ? 3 : 4;
    const int pw0 = pwg * 4;
    int wsA[4], weA[4];
#pragma unroll
    for (int i = 0; i < 4; i++) {
        const int qk = __shfl_sync(0xffffffffu, v, 8 + pw0 + (i < npw ? i : 0));
        wsA[i] = (qk >> 16) & 0xff;
        weA[i] = (qk >> 24) & 0xff;
        if (i >= npw) { wsA[i] = 0; weA[i] = 0; }
    }
    const int phN = half ? 3 : 4;
    const int ph0 = half ? 4 : 0;

    // per-lane offset within a position (channel slice)
    const size_t choff = (size_t)n * NPOS * NC4 + chid * 32 + lane;
    const float4 NI4 = make_float4(NEG_INF, NEG_INF, NEG_INF, NEG_INF);

    for (int phi = 0; phi < phN; phi++) {
        const int hk = __shfl_sync(0xffffffffu, v, 1 + ph0 + phi);
        const int hs = hk & 0xff;
        const int he = (hk >> 8) & 0xff;
        const int h2 = (hk >> 16) & 0xff;
        const int k  = (hk >> 24) & 0xff;
        const bool hnon = hs < he;

        const float4* __restrict__ tab = g_tab + (size_t)k * LEVS + choff;
        const float4* __restrict__ rowA = tab + (size_t)hs * FW * NC4;
        const float4* __restrict__ rowB = tab + (size_t)h2 * FW * NC4;

#pragma unroll
        for (int i = 0; i < 4; i++) {
            if (i >= npw) break;
            const int ws = wsA[i], we = weA[i];
            float4 acc = NI4;
            if (hnon && ws < we) {
                const float4* pA = rowA + (size_t)ws * NC4;
                const float4* pB = rowB + (size_t)ws * NC4;
                const int cnt = we - ws;
                int w = 0;
                for (; w + 2 <= cnt; w += 2) {        // 4 loads in flight
                    const float4 a0 = pA[0];
                    const float4 b0 = pB[0];
                    const float4 a1 = pA[NC4];
                    const float4 b1 = pB[NC4];
                    fmax4(acc, a0); fmax4(acc, b0);
                    fmax4(acc, a1); fmax4(acc, b1);
                    pA += 2 * NC4; pB += 2 * NC4;
                }
                if (w < cnt) {
                    const float4 a0 = pA[0];
                    const float4 b0 = pB[0];
                    fmax4(acc, a0); fmax4(acc, b0);
                }
            }
            // empty bin / all -inf -> 0.0 per reference isfinite rule
            const int b = phi * PP + pw0 + i;
            float* s = sbin + b * SSTR + chid * 128 + lane * 4;
            s[0] = (acc.x == NEG_INF) ? 0.0f : acc.x;
            s[1] = (acc.y == NEG_INF) ? 0.0f : acc.y;
            s[2] = (acc.z == NEG_INF) ? 0.0f : acc.z;
            s[3] = (acc.w == NEG_INF) ? 0.0f : acc.w;
        }
    }
    __syncthreads();

    // flush: out[r][ch][half ? 28+b : b]
    const size_t ob = (size_t)r * (NC * 49) + (half ? NB0 : 0);
    if (half == 0) {
        for (int i = tid; i < NB0 * NC; i += 256) {
            const int ch = i / NB0;
            const int b  = i - ch * NB0;
            out[ob + ch * 49 + b] = sbin[b * SSTR + ch];
        }
    } else {
        for (int i = tid; i < NB1 * NC; i += 256) {
            const int ch = i / NB1;
            const int b  = i - ch * NB1;
            out[ob + ch * 49 + b] = sbin[b * SSTR + ch];
        }
    }
}

extern "C" void kernel_launch(void* const* d_in, const int* in_sizes, int n_in,
                              void* d_out, int out_size)
{
    const float* x    = (const float*)d_in[0];
    const float* rois = (const float*)d_in[1];
    const int*   ridx = (const int*)d_in[2];
    float*       out  = (float*)d_out;
    const int R = in_sizes[2];

    cudaFuncSetAttribute(roi_pool, cudaFuncAttributeMaxDynamicSharedMemorySize,
                         SMEMB);

    dim3 tgrid((NPOS + 31) / 32, NC / 32, 4);
    transpose_kernel<<<tgrid, dim3(32, 8)>>>(x);
    for (int k = 1; k <= 3; k++) {
        const int rows  = FH - (1 << k) + 1;
        const int total = 4 * rows * FW * NC4;
        build_level<<<(total + 255) / 256, 256>>>(k, rows);
    }
    roi_prep<<<(R + 255) / 256, 256>>>(rois, ridx, R);
    roi_pool<<<R * 2, 256, SMEMB>>>(out, R);
}